// round 16
// baseline (speedup 1.0000x reference)
#include <cuda_runtime.h>
#include <cuda_fp16.h>
#include <mma.h>
#include <math.h>
#include <stdint.h>

using namespace nvcuda;

// Problem constants: N=100000, F=256, UNITS=256, DIM=128
#define F_DIM   256
#define UNITS   256
#define DIM     128
#define N_MAX   100000
#define M_TILE  64
#define THREADS 256
#define LDA     264          // A smem leading dim (halfs), 528B stride
#define LDB     72           // B smem leading dim (halfs), 144B stride
#define LDC     260          // C smem leading dim (floats), 1040B stride
#define KC      64           // K chunk per pipeline stage
#define NCHUNK  (F_DIM / KC) // 4
#define NBUF    2            // pipeline depth
#define GRID_P  296          // persistent grid: 2 CTAs x 148 SMs

// Static chunk->buffer map. CRITICAL: chunk 0 -> buf 1 (epilogue C overlaps
// A+buf0; the chunk-0 prefetch in flight during the epilogue lands in buf1).
#define CHUNK_BUF(c) (((c) & 1) ^ 1)

// Scratch
__device__ __half g_xh[(size_t)N_MAX * UNITS];   // packed [mean|var] fp16, ~51 MB
__device__ int    g_rowptr[N_MAX + 1];
__device__ float  g_kl;
__device__ __half g_Wh[UNITS * F_DIM];           // W^T fp16, [n][k]

__device__ __forceinline__ uint32_t smem_u32(const void* p) {
    uint32_t a;
    asm("{ .reg .u64 t; cvta.to.shared.u64 t, %1; cvt.u32.u64 %0, t; }"
        : "=r"(a) : "l"(p));
    return a;
}
__device__ __forceinline__ void cp_async16(uint32_t dst, const void* src) {
    asm volatile("cp.async.cg.shared.global [%0], [%1], 16;"
                 :: "r"(dst), "l"(src) : "memory");
}
#define CP_COMMIT()  asm volatile("cp.async.commit_group;" ::: "memory")
#define CP_WAIT(n)   asm volatile("cp.async.wait_group %0;" :: "n"(n) : "memory")

// f32x2 packed helpers (proven in R2): 2 fp32 FMAs per instruction, fp32-exact
__device__ __forceinline__ unsigned long long pack_dup(float a) {
    unsigned long long r;
    asm("mov.b64 %0, {%1, %1};" : "=l"(r) : "r"(__float_as_uint(a)));
    return r;
}
__device__ __forceinline__ unsigned long long pack2(float lo, float hi) {
    unsigned long long r;
    asm("mov.b64 %0, {%1, %2};" : "=l"(r) : "r"(__float_as_uint(lo)), "r"(__float_as_uint(hi)));
    return r;
}
__device__ __forceinline__ unsigned long long fma2(unsigned long long a,
                                                   unsigned long long b,
                                                   unsigned long long c) {
    unsigned long long d;
    asm("fma.rn.f32x2 %0, %1, %2, %3;" : "=l"(d) : "l"(a), "l"(b), "l"(c));
    return d;
}
__device__ __forceinline__ void unpack2(unsigned long long v, float& lo, float& hi) {
    unsigned int a, b;
    asm("mov.b64 {%0, %1}, %2;" : "=r"(a), "=r"(b) : "l"(v));
    lo = __uint_as_float(a);
    hi = __uint_as_float(b);
}

// ---------------------------------------------------------------------------
// Kernel 1: W fp16 transpose + kl zero + vectorized CSR rowptr scatter
// ---------------------------------------------------------------------------
__global__ void prep_kernel(const int* __restrict__ row,
                            const float* __restrict__ W, int n, int e) {
    const int i = blockIdx.x * blockDim.x + threadIdx.x;
    if (i == 0) g_kl = 0.0f;
    if (i < UNITS * F_DIM) {      // W transpose + fp16 round
        const int nn = i / F_DIM, kk = i % F_DIM;
        g_Wh[i] = __float2half(W[kk * UNITS + nn]);
    }
    const int j0 = i * 4;
    if (j0 > e) return;
    int r[5];
    r[0] = (j0 == 0) ? -1 : __ldg(&row[j0 - 1]);
    if (j0 + 3 < e) {
        const int4 v = *reinterpret_cast<const int4*>(row + j0);
        r[1] = v.x; r[2] = v.y; r[3] = v.z; r[4] = v.w;
    } else {
#pragma unroll
        for (int u = 0; u < 4; u++)
            r[1 + u] = (j0 + u < e) ? __ldg(&row[j0 + u]) : n;
    }
#pragma unroll
    for (int u = 0; u < 4; u++) {
        const int j = j0 + u;
        if (j > e) break;
        const int prev = r[u];
        const int cur  = (j == e) ? n : r[u + 1];
        for (int k = prev + 1; k <= cur; k++) g_rowptr[k] = j;
    }
}

// ---------------------------------------------------------------------------
// Kernel 2: persistent single-pass fp16 WMMA GEMM (frozen from R15)
// ---------------------------------------------------------------------------
__global__ __launch_bounds__(THREADS, 2) void gemm_wmma_kernel(
    const float* __restrict__ feat, int n, int ntiles)
{
    extern __shared__ char smem[];
    __half* Ah = reinterpret_cast<__half*>(smem);        // [0, 33792)
    __half* Bbase = Ah + M_TILE * LDA;                   // buf0 [33792,70656), buf1 [70656,107520)
    float* C = reinterpret_cast<float*>(smem);           // [0, 66560) = A + buf0 only

    const int tid = threadIdx.x;
    const int wid = tid >> 5, lane = tid & 31;
    const int rg = wid >> 2;
    const int cg = wid & 3;
    const int BUF_ELEMS = 256 * LDB;

    {   // initial prefetch: chunk 0 -> buf1
        __half* Bh = Bbase + CHUNK_BUF(0) * BUF_ELEMS;
#pragma unroll
        for (int it = 0; it < 8; it++) {
            const int g = it * THREADS + tid;
            const int nn = g >> 3;
            const int k8 = (g & 7) << 3;
            cp_async16(smem_u32(Bh + nn * LDB + k8), g_Wh + (size_t)nn * F_DIM + k8);
        }
        CP_COMMIT();
    }

    float kl = 0.f;

    for (int tile = blockIdx.x; tile < ntiles; tile += gridDim.x) {
        const int row0 = tile * M_TILE;
        const int nrows = min(M_TILE, n - row0);
        const bool tile_has_next = (tile + gridDim.x) < ntiles;

        // --- stage A: fp32 -> fp16 ---
#pragma unroll
        for (int it = 0; it < 16; it++) {
            const int j = it * THREADS + tid;
            const int r = j >> 6;
            const int c4 = (j & 63) << 2;
            float4 v = make_float4(0.f, 0.f, 0.f, 0.f);
            if (r < nrows)
                v = reinterpret_cast<const float4*>(feat + (size_t)(row0 + r) * F_DIM)[j & 63];
            __half2 p0; p0.x = __float2half(v.x); p0.y = __float2half(v.y);
            __half2 p1; p1.x = __float2half(v.z); p1.y = __float2half(v.w);
            reinterpret_cast<__half2*>(Ah + r * LDA + c4)[0] = p0;
            reinterpret_cast<__half2*>(Ah + r * LDA + c4)[1] = p1;
        }

        wmma::fragment<wmma::accumulator, 16, 16, 16, float> acc[2][4];
#pragma unroll
        for (int i = 0; i < 2; i++)
#pragma unroll
            for (int j = 0; j < 4; j++) wmma::fill_fragment(acc[i][j], 0.0f);

        for (int c = 0; c < NCHUNK; c++) {
            CP_WAIT(0);
            __syncthreads();

            const bool have_next = (c < NCHUNK - 1) || tile_has_next;
            if (have_next) {
                const int cn = (c + 1) & (NCHUNK - 1);
                const int kcn = cn * KC;
                __half* Bh = Bbase + CHUNK_BUF(cn) * BUF_ELEMS;
#pragma unroll
                for (int it = 0; it < 8; it++) {
                    const int g = it * THREADS + tid;
                    const int nn = g >> 3;
                    const int k8 = (g & 7) << 3;
                    cp_async16(smem_u32(Bh + nn * LDB + k8),
                               g_Wh + (size_t)nn * F_DIM + kcn + k8);
                }
                CP_COMMIT();
            }

            const int kc = c * KC;
            const __half* Bh = Bbase + CHUNK_BUF(c) * BUF_ELEMS;
#pragma unroll
            for (int ks = 0; ks < KC; ks += 16) {
                wmma::fragment<wmma::matrix_a, 16, 16, 16, __half, wmma::row_major> fah[2];
#pragma unroll
                for (int i = 0; i < 2; i++)
                    wmma::load_matrix_sync(fah[i], Ah + (rg * 32 + i * 16) * LDA + kc + ks, LDA);
#pragma unroll
                for (int j = 0; j < 4; j++) {
                    const int ncol = cg * 64 + j * 16;
                    wmma::fragment<wmma::matrix_b, 16, 16, 16, __half, wmma::col_major> fbh;
                    wmma::load_matrix_sync(fbh, Bh + ncol * LDB + ks, LDB);
                    wmma::mma_sync(acc[0][j], fah[0], fbh, acc[0][j]);
                    wmma::mma_sync(acc[1][j], fah[1], fbh, acc[1][j]);
                }
            }
        }
        __syncthreads();   // A+buf0 free -> C; chunk-0 prefetch flies into buf1

#pragma unroll
        for (int i = 0; i < 2; i++)
#pragma unroll
            for (int j = 0; j < 4; j++)
                wmma::store_matrix_sync(C + (rg * 32 + i * 16) * LDC + cg * 64 + j * 16,
                                        acc[i][j], LDC, wmma::mem_row_major);
        __syncthreads();

        // --- epilogue: activations via MUFU, KL; g_x in fp16 ---
#pragma unroll
        for (int it = 0; it < 16; it++) {
            const int idx = it * THREADS + tid;
            const int r = idx >> 6;
            const int d2 = (idx & 63) << 1;
            if (r < nrows) {
                float mo[2], vo[2];
#pragma unroll
                for (int q = 0; q < 2; q++) {
                    const float hm = C[r * LDC + d2 + q];
                    const float hv = C[r * LDC + DIM + d2 + q];
                    const float m = hm > 0.f ? hm : (__expf(hm) - 1.0f);
                    const float v = hv > 0.f ? hv : 0.f;
                    const float att = __expf(-v);
                    kl += m * m + v - __logf(1e-8f + v) - 1.f;
                    mo[q] = m * att;
                    vo[q] = v * att * att;
                }
                const size_t base = (size_t)(row0 + r) * UNITS;
                __half2 hm2; hm2.x = __float2half(mo[0]); hm2.y = __float2half(mo[1]);
                __half2 hv2; hv2.x = __float2half(vo[0]); hv2.y = __float2half(vo[1]);
                *reinterpret_cast<__half2*>(g_xh + base + d2)       = hm2;
                *reinterpret_cast<__half2*>(g_xh + base + DIM + d2) = hv2;
            }
        }
        __syncthreads();
    }

    kl *= 0.5f / (float)DIM;
    __shared__ float kl_red[8];
#pragma unroll
    for (int off = 16; off > 0; off >>= 1)
        kl += __shfl_down_sync(0xFFFFFFFFu, kl, off);
    if (lane == 0) kl_red[wid] = kl;
    __syncthreads();
    if (tid == 0) {
        float s = 0.f;
#pragma unroll
        for (int i = 0; i < 8; i++) s += kl_red[i];
        atomicAdd(&g_kl, s);
    }
}

// ---------------------------------------------------------------------------
// Kernel 3: fused dual SpMM with f32x2 packed accumulation.
// ONE warp per node: lanes 0-15 = mean half (adj1), lanes 16-31 = var (adj2).
// Per edge-lane: 4 fma2 replace 8 FFMA (FMA-pipe pressure was the binding
// constraint per R8 profile: fma=34%, issue=49%, L2 only 46%).
// ---------------------------------------------------------------------------
__global__ void spmm_kernel(
    const int* __restrict__ col,
    const float* __restrict__ a1,
    const float* __restrict__ a2,
    float* __restrict__ out,
    int n, int write_kl)
{
    const int gtid = blockIdx.x * blockDim.x + threadIdx.x;
    if (gtid == 0 && write_kl) out[(size_t)n * UNITS] = g_kl;

    const int node = gtid >> 5;
    const int lane = threadIdx.x & 31;
    if (node >= n) return;

    const int s = g_rowptr[node];
    const int e = g_rowptr[node + 1];
    const float* __restrict__ wa = (lane < 16) ? a1 : a2;

    unsigned long long acc2[4];
#pragma unroll
    for (int q = 0; q < 4; q++) acc2[q] = 0ull;

    int i = s;
    for (; i + 3 < e; i += 4) {
        int   c[4];
        float w[4];
        uint4 x[4];
#pragma unroll
        for (int u = 0; u < 4; u++) { c[u] = __ldg(&col[i + u]); w[u] = __ldg(&wa[i + u]); }
#pragma unroll
        for (int u = 0; u < 4; u++)
            x[u] = __ldg(reinterpret_cast<const uint4*>(g_xh + (size_t)c[u] * UNITS) + lane);
#pragma unroll
        for (int u = 0; u < 4; u++) {
            const unsigned long long w2 = pack_dup(w[u]);
            const __half2* hp = reinterpret_cast<const __half2*>(&x[u]);
#pragma unroll
            for (int q = 0; q < 4; q++) {
                const float2 f = __half22float2(hp[q]);
                acc2[q] = fma2(pack2(f.x, f.y), w2, acc2[q]);
            }
        }
    }
    for (; i < e; i++) {
        const int c0 = __ldg(&col[i]);
        const unsigned long long w2 = pack_dup(__ldg(&wa[i]));
        const uint4 x0 = __ldg(reinterpret_cast<const uint4*>(g_xh + (size_t)c0 * UNITS) + lane);
        const __half2* hp = reinterpret_cast<const __half2*>(&x0);
#pragma unroll
        for (int q = 0; q < 4; q++) {
            const float2 f = __half22float2(hp[q]);
            acc2[q] = fma2(pack2(f.x, f.y), w2, acc2[q]);
        }
    }

    float acc[8];
#pragma unroll
    for (int q = 0; q < 4; q++) unpack2(acc2[q], acc[2 * q], acc[2 * q + 1]);

    float* o = out + (size_t)node * UNITS + lane * 8;
    __stcs(reinterpret_cast<float4*>(o),     make_float4(acc[0], acc[1], acc[2], acc[3]));
    __stcs(reinterpret_cast<float4*>(o + 4), make_float4(acc[4], acc[5], acc[6], acc[7]));
}

// ---------------------------------------------------------------------------
extern "C" void kernel_launch(void* const* d_in, const int* in_sizes, int n_in,
                              void* d_out, int out_size) {
    const float* feat = (const float*)d_in[0];
    const float* W    = (const float*)d_in[1];
    const int*   row  = (const int*)d_in[2];
    const int*   col  = (const int*)d_in[3];
    const float* a1   = (const float*)d_in[4];
    const float* a2   = (const float*)d_in[5];
    float* out = (float*)d_out;

    const int n = in_sizes[0] / F_DIM;
    const int e = in_sizes[2];
    const int write_kl = (out_size > n * UNITS) ? 1 : 0;

    {   // fused prep
        const int threads = 256;
        const int scatter_threads = (e + 4) / 4 + 1;
        const int work = (scatter_threads > UNITS * F_DIM) ? scatter_threads : UNITS * F_DIM;
        prep_kernel<<<(work + threads - 1) / threads, threads>>>(row, W, n, e);
    }
    {   // persistent fp16 WMMA GEMM + epilogue (107.5KB smem, 2 CTAs/SM)
        const int ntiles = (n + M_TILE - 1) / M_TILE;
        const int grid = ntiles < GRID_P ? ntiles : GRID_P;
        const int smem_total = M_TILE * LDA * 2 + NBUF * (256 * LDB) * 2; // 107520
        cudaFuncSetAttribute(gemm_wmma_kernel,
                             cudaFuncAttributeMaxDynamicSharedMemorySize, smem_total);
        gemm_wmma_kernel<<<grid, THREADS, smem_total>>>(feat, n, ntiles);
    }
    {   // dual SpMM, 1 warp per node
        const int threads = 256;
        spmm_kernel<<<(n * 32 + threads - 1) / threads, threads>>>(col, a1, a2, out, n, write_kl);
    }
}

// round 17
// speedup vs baseline: 1.0367x; 1.0367x over previous
#include <cuda_runtime.h>
#include <cuda_fp16.h>
#include <mma.h>
#include <math.h>
#include <stdint.h>

using namespace nvcuda;

// Problem constants: N=100000, F=256, UNITS=256, DIM=128
#define F_DIM   256
#define UNITS   256
#define DIM     128
#define N_MAX   100000
#define M_TILE  64
#define THREADS 256
#define LDA     264          // A smem leading dim (halfs), 528B stride
#define LDBF    264          // resident-B smem leading dim (halfs), 528B stride
#define LDC     260          // C smem leading dim (floats), 1040B stride

// SMEM map (bytes): Bfull [0, 135168); region2 [135168, 201728)
//   region2 holds Ah (33792B) during mainloop, reused as C (66560B) in epilogue.
#define SMEM_B_BYTES   (256 * LDBF * 2)          // 135168
#define SMEM_TOTAL     (SMEM_B_BYTES + M_TILE * LDC * 4)  // 201728

// Scratch
__device__ __half g_xh[(size_t)N_MAX * UNITS];   // packed [mean|var] fp16, ~51 MB
__device__ int    g_rowptr[N_MAX + 1];
__device__ float  g_kl;
__device__ __half g_Wh[UNITS * F_DIM];           // W^T fp16, [n][k]

__device__ __forceinline__ uint32_t smem_u32(const void* p) {
    uint32_t a;
    asm("{ .reg .u64 t; cvta.to.shared.u64 t, %1; cvt.u32.u64 %0, t; }"
        : "=r"(a) : "l"(p));
    return a;
}
__device__ __forceinline__ void cp_async16(uint32_t dst, const void* src) {
    asm volatile("cp.async.cg.shared.global [%0], [%1], 16;"
                 :: "r"(dst), "l"(src) : "memory");
}
#define CP_COMMIT()  asm volatile("cp.async.commit_group;" ::: "memory")
#define CP_WAIT(n)   asm volatile("cp.async.wait_group %0;" :: "n"(n) : "memory")

// ---------------------------------------------------------------------------
// Kernel 1: W fp16 transpose (COALESCED reads, scattered 2B writes)
// + kl zero + vectorized CSR rowptr scatter.
// ---------------------------------------------------------------------------
__global__ void prep_kernel(const int* __restrict__ row,
                            const float* __restrict__ W, int n, int e) {
    const int i = blockIdx.x * blockDim.x + threadIdx.x;
    if (i == 0) g_kl = 0.0f;
    if (i < UNITS * F_DIM) {
        // coalesced read of W[i] (i = kk*UNITS + nn), scattered 2B write
        const int kk = i >> 8;           // K index (row of W)
        const int nn = i & 255;          // N index (col of W)
        g_Wh[nn * F_DIM + kk] = __float2half(W[i]);
    }
    const int j0 = i * 4;
    if (j0 > e) return;
    int r[5];
    r[0] = (j0 == 0) ? -1 : __ldg(&row[j0 - 1]);
    if (j0 + 3 < e) {
        const int4 v = *reinterpret_cast<const int4*>(row + j0);
        r[1] = v.x; r[2] = v.y; r[3] = v.z; r[4] = v.w;
    } else {
#pragma unroll
        for (int u = 0; u < 4; u++)
            r[1 + u] = (j0 + u < e) ? __ldg(&row[j0 + u]) : n;
    }
#pragma unroll
    for (int u = 0; u < 4; u++) {
        const int j = j0 + u;
        if (j > e) break;
        const int prev = r[u];
        const int cur  = (j == e) ? n : r[u + 1];
        for (int k = prev + 1; k <= cur; k++) g_rowptr[k] = j;
    }
}

// ---------------------------------------------------------------------------
// Kernel 2: persistent fp16 WMMA GEMM with FULLY B-RESIDENT smem.
// B (128KB data, 135KB padded) loaded ONCE per CTA via cp.async; the
// mainloop has no async waits and no per-chunk barriers: per tile it is
// stage A -> sync -> 16 uninterrupted k-steps of LDS+HMMA -> sync -> C ->
// epilogue -> sync. 1 CTA/SM (201.7KB smem), 256 threads, grid = 148.
// ---------------------------------------------------------------------------
__global__ __launch_bounds__(THREADS) void gemm_wmma_kernel(
    const float* __restrict__ feat, int n, int ntiles)
{
    extern __shared__ char smem[];
    __half* Bf = reinterpret_cast<__half*>(smem);                // [0, 135168)
    __half* Ah = reinterpret_cast<__half*>(smem + SMEM_B_BYTES); // region2 as A
    float*  C  = reinterpret_cast<float*>(smem + SMEM_B_BYTES);  // region2 as C

    const int tid = threadIdx.x;
    const int wid = tid >> 5, lane = tid & 31;
    const int rg = wid >> 2;            // 0..1 (32-row group)
    const int cg = wid & 3;             // 0..3 (64-col group)

    // --- load FULL B once: 256 rows x 256 halfs (32 x 16B per row) ---
    {
#pragma unroll
        for (int it = 0; it < 32; it++) {
            const int g = it * THREADS + tid;    // 0..8191
            const int nn = g >> 5;               // 0..255
            const int k8 = (g & 31) << 3;        // 0..248
            cp_async16(smem_u32(Bf + nn * LDBF + k8),
                       g_Wh + (size_t)nn * F_DIM + k8);
        }
        CP_COMMIT();
    }

    float kl = 0.f;
    bool b_waited = false;

    for (int tile = blockIdx.x; tile < ntiles; tile += gridDim.x) {
        const int row0 = tile * M_TILE;
        const int nrows = min(M_TILE, n - row0);

        // --- stage A: fp32 -> fp16 (B load flies underneath on first tile) ---
#pragma unroll
        for (int it = 0; it < 16; it++) {
            const int j = it * THREADS + tid;    // float4 id, 0..4095
            const int r = j >> 6;                // row 0..63
            const int c4 = (j & 63) << 2;
            float4 v = make_float4(0.f, 0.f, 0.f, 0.f);
            if (r < nrows)
                v = reinterpret_cast<const float4*>(feat + (size_t)(row0 + r) * F_DIM)[j & 63];
            __half2 p0; p0.x = __float2half(v.x); p0.y = __float2half(v.y);
            __half2 p1; p1.x = __float2half(v.z); p1.y = __float2half(v.w);
            reinterpret_cast<__half2*>(Ah + r * LDA + c4)[0] = p0;
            reinterpret_cast<__half2*>(Ah + r * LDA + c4)[1] = p1;
        }
        if (!b_waited) { CP_WAIT(0); b_waited = true; }
        __syncthreads();   // A staged (and B resident)

        wmma::fragment<wmma::accumulator, 16, 16, 16, float> acc[2][4];
#pragma unroll
        for (int i = 0; i < 2; i++)
#pragma unroll
            for (int j = 0; j < 4; j++) wmma::fill_fragment(acc[i][j], 0.0f);

        // --- mainloop: 16 k-steps, no barriers, no async waits ---
#pragma unroll 4
        for (int ks = 0; ks < F_DIM; ks += 16) {
            wmma::fragment<wmma::matrix_a, 16, 16, 16, __half, wmma::row_major> fah[2];
#pragma unroll
            for (int i = 0; i < 2; i++)
                wmma::load_matrix_sync(fah[i], Ah + (rg * 32 + i * 16) * LDA + ks, LDA);
#pragma unroll
            for (int j = 0; j < 4; j++) {
                const int ncol = cg * 64 + j * 16;
                wmma::fragment<wmma::matrix_b, 16, 16, 16, __half, wmma::col_major> fbh;
                wmma::load_matrix_sync(fbh, Bf + ncol * LDBF + ks, LDBF);
                wmma::mma_sync(acc[0][j], fah[0], fbh, acc[0][j]);
                wmma::mma_sync(acc[1][j], fah[1], fbh, acc[1][j]);
            }
        }
        __syncthreads();   // all warps done reading Ah -> region2 becomes C

#pragma unroll
        for (int i = 0; i < 2; i++)
#pragma unroll
            for (int j = 0; j < 4; j++)
                wmma::store_matrix_sync(C + (rg * 32 + i * 16) * LDC + cg * 64 + j * 16,
                                        acc[i][j], LDC, wmma::mem_row_major);
        __syncthreads();

        // --- epilogue: activations via MUFU, KL; g_x in fp16 ---
#pragma unroll
        for (int it = 0; it < 16; it++) {
            const int idx = it * THREADS + tid;  // 0..4095
            const int r = idx >> 6;              // 0..63
            const int d2 = (idx & 63) << 1;      // even d, 0..126
            if (r < nrows) {
                float mo[2], vo[2];
#pragma unroll
                for (int q = 0; q < 2; q++) {
                    const float hm = C[r * LDC + d2 + q];
                    const float hv = C[r * LDC + DIM + d2 + q];
                    const float m = hm > 0.f ? hm : (__expf(hm) - 1.0f);
                    const float v = hv > 0.f ? hv : 0.f;
                    const float att = __expf(-v);
                    kl += m * m + v - __logf(1e-8f + v) - 1.f;
                    mo[q] = m * att;
                    vo[q] = v * att * att;
                }
                const size_t base = (size_t)(row0 + r) * UNITS;
                __half2 hm2; hm2.x = __float2half(mo[0]); hm2.y = __float2half(mo[1]);
                __half2 hv2; hv2.x = __float2half(vo[0]); hv2.y = __float2half(vo[1]);
                *reinterpret_cast<__half2*>(g_xh + base + d2)       = hm2;
                *reinterpret_cast<__half2*>(g_xh + base + DIM + d2) = hv2;
            }
        }
        __syncthreads();   // C reads done before next tile's A staging
    }

    // --- final KL reduction (once per CTA) ---
    kl *= 0.5f / (float)DIM;
    __shared__ float kl_red[8];
#pragma unroll
    for (int off = 16; off > 0; off >>= 1)
        kl += __shfl_down_sync(0xFFFFFFFFu, kl, off);
    if (lane == 0) kl_red[wid] = kl;
    __syncthreads();
    if (tid == 0) {
        float s = 0.f;
#pragma unroll
        for (int i = 0; i < 8; i++) s += kl_red[i];
        atomicAdd(&g_kl, s);
    }
}

// ---------------------------------------------------------------------------
// Kernel 3: fused dual SpMM on fp16 table (R15 version — f32x2 regressed).
// ONE warp per node: lanes 0-15 = mean half (adj1), lanes 16-31 = var (adj2).
// ---------------------------------------------------------------------------
__global__ void spmm_kernel(
    const int* __restrict__ col,
    const float* __restrict__ a1,
    const float* __restrict__ a2,
    float* __restrict__ out,
    int n, int write_kl)
{
    const int gtid = blockIdx.x * blockDim.x + threadIdx.x;
    if (gtid == 0 && write_kl) out[(size_t)n * UNITS] = g_kl;

    const int node = gtid >> 5;
    const int lane = threadIdx.x & 31;
    if (node >= n) return;

    const int s = g_rowptr[node];
    const int e = g_rowptr[node + 1];
    const float* __restrict__ wa = (lane < 16) ? a1 : a2;

    float acc[8];
#pragma unroll
    for (int q = 0; q < 8; q++) acc[q] = 0.f;

    int i = s;
    for (; i + 3 < e; i += 4) {
        int   c[4];
        float w[4];
        uint4 x[4];
#pragma unroll
        for (int u = 0; u < 4; u++) { c[u] = __ldg(&col[i + u]); w[u] = __ldg(&wa[i + u]); }
#pragma unroll
        for (int u = 0; u < 4; u++)
            x[u] = __ldg(reinterpret_cast<const uint4*>(g_xh + (size_t)c[u] * UNITS) + lane);
#pragma unroll
        for (int u = 0; u < 4; u++) {
            const __half2* hp = reinterpret_cast<const __half2*>(&x[u]);
#pragma unroll
            for (int q = 0; q < 4; q++) {
                const float2 f = __half22float2(hp[q]);
                acc[2 * q]     = fmaf(w[u], f.x, acc[2 * q]);
                acc[2 * q + 1] = fmaf(w[u], f.y, acc[2 * q + 1]);
            }
        }
    }
    for (; i < e; i++) {
        const int c0 = __ldg(&col[i]);
        const float w0 = __ldg(&wa[i]);
        const uint4 x0 = __ldg(reinterpret_cast<const uint4*>(g_xh + (size_t)c0 * UNITS) + lane);
        const __half2* hp = reinterpret_cast<const __half2*>(&x0);
#pragma unroll
        for (int q = 0; q < 4; q++) {
            const float2 f = __half22float2(hp[q]);
            acc[2 * q]     = fmaf(w0, f.x, acc[2 * q]);
            acc[2 * q + 1] = fmaf(w0, f.y, acc[2 * q + 1]);
        }
    }

    float* o = out + (size_t)node * UNITS + lane * 8;
    __stcs(reinterpret_cast<float4*>(o),     make_float4(acc[0], acc[1], acc[2], acc[3]));
    __stcs(reinterpret_cast<float4*>(o + 4), make_float4(acc[4], acc[5], acc[6], acc[7]));
}

// ---------------------------------------------------------------------------
extern "C" void kernel_launch(void* const* d_in, const int* in_sizes, int n_in,
                              void* d_out, int out_size) {
    const float* feat = (const float*)d_in[0];
    const float* W    = (const float*)d_in[1];
    const int*   row  = (const int*)d_in[2];
    const int*   col  = (const int*)d_in[3];
    const float* a1   = (const float*)d_in[4];
    const float* a2   = (const float*)d_in[5];
    float* out = (float*)d_out;

    const int n = in_sizes[0] / F_DIM;
    const int e = in_sizes[2];
    const int write_kl = (out_size > n * UNITS) ? 1 : 0;

    {   // fused prep
        const int threads = 256;
        const int scatter_threads = (e + 4) / 4 + 1;
        const int work = (scatter_threads > UNITS * F_DIM) ? scatter_threads : UNITS * F_DIM;
        prep_kernel<<<(work + threads - 1) / threads, threads>>>(row, W, n, e);
    }
    {   // persistent B-resident fp16 WMMA GEMM (201.7KB smem, 1 CTA/SM)
        const int ntiles = (n + M_TILE - 1) / M_TILE;
        const int grid = ntiles < 148 ? ntiles : 148;
        cudaFuncSetAttribute(gemm_wmma_kernel,
                             cudaFuncAttributeMaxDynamicSharedMemorySize, SMEM_TOTAL);
        gemm_wmma_kernel<<<grid, THREADS, SMEM_TOTAL>>>(feat, n, ntiles);
    }
    {   // dual SpMM, 1 warp per node
        const int threads = 256;
        spmm_kernel<<<(n * 32 + threads - 1) / threads, threads>>>(col, a1, a2, out, n, write_kl);
    }
}